// round 15
// baseline (speedup 1.0000x reference)
#include <cuda_runtime.h>
#include <cuda_fp16.h>

// ---------------------------------------------------------------------------
// LSTM_6786048328562 : T=512, B=32, I=H=1024  (fp32 in/out, fp16 tensor math
//   with fp32 accumulate)
//   out = [ output(512*32*1024) | h_n(32*1024) | c_n(32*1024) ]
//
// Row reorder:  j'' = 32*blk + gate*8 + u   (hidden n = 8*blk + u, blk=0..127)
//
// prep  : reorder+fp16-round W,U; fp16 x; bias; zero h; g_bar=0; xg counters=0
// fused : ONE kernel, 148 CTAs (one per SM).
//         pre-phase: ALL CTAs compute xg M-blocks 0..47 (1536 tiles).
//         then: CTAs 0..127  -> persistent recurrence (R12 structure,
//                               single-counter release/acquire barrier);
//               CTAs 128..147 -> gemm workers streaming M-blocks 48..127
//                               (m-major), publishing per-block counters.
//         lstm polls the counter of the M-block needed 2 steps ahead inside
//         its existing barrier spin (off critical path after warm-up).
// ---------------------------------------------------------------------------

#define T_STEPS 512
#define BATCH   32
#define HID     1024
#define GATES   4096
#define PRE_TILES 1536            // 48 M-blocks x 32 N-tiles

__device__ float  d_xg[67108864];            // [16384][4096] fp32
__device__ __half d_xh[16777216];            // fp16 x
__device__ __half d_Wh[GATES * HID];
__device__ __half d_Uh[GATES * HID];
__device__ float  d_biasp[GATES];
__device__ __half d_hbuf[2 * BATCH * HID];   // double-buffered h (fp16)
__device__ unsigned g_bar;
__device__ unsigned g_xgdone[128 * 32];      // per-M-block tile counter, 128B stride

__device__ __forceinline__ void mma_f16(float* c, const unsigned* a, const unsigned* b) {
    asm volatile(
        "mma.sync.aligned.m16n8k16.row.col.f32.f16.f16.f32 "
        "{%0,%1,%2,%3}, {%4,%5,%6,%7}, {%8,%9}, {%0,%1,%2,%3};\n"
        : "+f"(c[0]), "+f"(c[1]), "+f"(c[2]), "+f"(c[3])
        : "r"(a[0]), "r"(a[1]), "r"(a[2]), "r"(a[3]), "r"(b[0]), "r"(b[1]));
}

__device__ __forceinline__ float sigm_f(float x) {
    float e = __expf(-x);
    return __fdividef(1.0f, 1.0f + e);
}
__device__ __forceinline__ float tanh_f(float x) {
    float xc = fminf(fmaxf(x, -10.0f), 10.0f);
    float e = __expf(2.0f * xc);
    return __fdividef(e - 1.0f, e + 1.0f);
}

#define CP_ASYNC_CG(dst, src) \
    asm volatile("cp.async.cg.shared.global [%0], [%1], 16;\n" :: "r"(dst), "l"(src))
#define CP_COMMIT() asm volatile("cp.async.commit_group;\n")
#define CP_WAIT(n)  asm volatile("cp.async.wait_group %0;\n" :: "n"(n))

// ---------------------------------------------------------------------------
__global__ void prep_kernel(const float* __restrict__ x,
                            const float* __restrict__ W, const float* __restrict__ U,
                            const float* __restrict__ bih, const float* __restrict__ bhh) {
    int tid = blockIdx.x * blockDim.x + threadIdx.x;
    int stride = gridDim.x * blockDim.x;
    if (tid == 0) g_bar = 0u;
    if (tid < 128 * 32) g_xgdone[tid] = 0u;

    for (int idx = tid; idx < GATES * HID; idx += stride) {
        int jp = idx >> 10, k = idx & 1023;
        int blk = jp >> 5, r = jp & 31;
        int gate = r >> 3, u = r & 7;
        int j = gate * HID + (blk * 8 + u);
        d_Wh[idx] = __float2half_rn(W[j * HID + k]);
        d_Uh[idx] = __float2half_rn(U[j * HID + k]);
    }
    for (int idx = tid; idx < 16777216; idx += stride)
        d_xh[idx] = __float2half_rn(x[idx]);
    for (int idx = tid; idx < GATES; idx += stride) {
        int blk = idx >> 5, r = idx & 31;
        int gate = r >> 3, u = r & 7;
        int j = gate * HID + (blk * 8 + u);
        d_biasp[idx] = bih[j] + bhh[j];
    }
    for (int idx = tid; idx < 2 * BATCH * HID; idx += stride)
        d_hbuf[idx] = __float2half_rn(0.0f);
}

// ---------------------------------------------------------------------------
// One 128x128x1024 xg tile (fp16 mma, 4-stage cp.async). All 256 threads.
// Publishes the tile into its M-block counter (release) at the end.
// ---------------------------------------------------------------------------
#define P1H 40
#define P1_STAGE (128 * P1H)

__device__ __noinline__ void gemm_tile(char* smcv, int mb, int nb) {
    __half* As = (__half*)smcv;
    __half* Bs = As + 4 * P1_STAGE;

    const int n0 = nb * 128;
    const int m0 = mb * 128;
    const int tid = threadIdx.x;
    const int warp = tid >> 5, lane = tid & 31;
    const int wm = warp >> 2, wn = warp & 3;
    const int gid = lane >> 2, tg = lane & 3;

    float acc[4][4][4];
#pragma unroll
    for (int i = 0; i < 4; i++)
#pragma unroll
        for (int j = 0; j < 4; j++)
#pragma unroll
            for (int k = 0; k < 4; k++) acc[i][j][k] = 0.0f;

    const __half* Ag = d_xh + (size_t)m0 * HID;
    const __half* Bg = d_Wh + (size_t)n0 * HID;

    auto load_stage = [&](int kt, int st) {
        __half* Ad = As + st * P1_STAGE;
        __half* Bd = Bs + st * P1_STAGE;
        const int k0 = kt * 32;
#pragma unroll
        for (int l = 0; l < 2; l++) {
            int i = tid + l * 256;
            int row = i >> 2, seg = i & 3;
            unsigned da = (unsigned)__cvta_generic_to_shared(Ad + row * P1H + seg * 8);
            CP_ASYNC_CG(da, Ag + (size_t)row * HID + k0 + seg * 8);
            unsigned db = (unsigned)__cvta_generic_to_shared(Bd + row * P1H + seg * 8);
            CP_ASYNC_CG(db, Bg + (size_t)row * HID + k0 + seg * 8);
        }
        CP_COMMIT();
    };

    load_stage(0, 0);
    load_stage(1, 1);
    load_stage(2, 2);
    for (int kt = 0; kt < 32; kt++) {
        if (kt < 30)       { CP_WAIT(2); }
        else if (kt == 30) { CP_WAIT(1); }
        else               { CP_WAIT(0); }
        __syncthreads();
        if (kt + 3 < 32) load_stage(kt + 3, (kt + 3) & 3);

        const __half* Ac = As + (kt & 3) * P1_STAGE;
        const __half* Bc = Bs + (kt & 3) * P1_STAGE;
#pragma unroll
        for (int ks = 0; ks < 2; ks++) {
            const int kb = ks * 16;
            unsigned a[4][4], b[4][2];
#pragma unroll
            for (int mf = 0; mf < 4; mf++) {
                int row = wm * 64 + mf * 16 + gid;
                a[mf][0] = *(const unsigned*)&Ac[row * P1H + kb + 2 * tg];
                a[mf][1] = *(const unsigned*)&Ac[(row + 8) * P1H + kb + 2 * tg];
                a[mf][2] = *(const unsigned*)&Ac[row * P1H + kb + 8 + 2 * tg];
                a[mf][3] = *(const unsigned*)&Ac[(row + 8) * P1H + kb + 8 + 2 * tg];
            }
#pragma unroll
            for (int nf = 0; nf < 4; nf++) {
                int col = wn * 32 + nf * 8 + gid;
                b[nf][0] = *(const unsigned*)&Bc[col * P1H + kb + 2 * tg];
                b[nf][1] = *(const unsigned*)&Bc[col * P1H + kb + 8 + 2 * tg];
            }
#pragma unroll
            for (int mf = 0; mf < 4; mf++)
#pragma unroll
                for (int nf = 0; nf < 4; nf++) mma_f16(acc[mf][nf], a[mf], b[nf]);
        }
    }
    __syncthreads();

#pragma unroll
    for (int mf = 0; mf < 4; mf++)
#pragma unroll
        for (int nf = 0; nf < 4; nf++) {
            int row = m0 + wm * 64 + mf * 16 + gid;
            int col = n0 + wn * 32 + nf * 8 + 2 * tg;
            float b0 = d_biasp[col], b1 = d_biasp[col + 1];
            d_xg[(size_t)row * GATES + col]           = acc[mf][nf][0] + b0;
            d_xg[(size_t)row * GATES + col + 1]       = acc[mf][nf][1] + b1;
            d_xg[(size_t)(row + 8) * GATES + col]     = acc[mf][nf][2] + b0;
            d_xg[(size_t)(row + 8) * GATES + col + 1] = acc[mf][nf][3] + b1;
        }
    __syncthreads();   // all STGs done before the release below (CTA-cumulative)
    if (tid == 0) {
        unsigned long long cp = (unsigned long long)
            __cvta_generic_to_global(&g_xgdone[mb * 32]);
        asm volatile("red.release.gpu.global.add.u32 [%0], %1;"
                     :: "l"(cp), "r"(1u) : "memory");
    }
}

// ---------------------------------------------------------------------------
// Fused kernel. 148 CTAs x 256 threads, 1 CTA/SM.
// smem layout (lstm):  hs 8 x 4352 half | rb | xs   (gemm uses first 80KB)
// ---------------------------------------------------------------------------
#define SLC_ROW 136
#define SLC_HALF (16 * SLC_ROW)
#define SLC_WARP (2 * SLC_HALF)
#define HS_BYTES (8 * SLC_WARP * 2)          // 69,632
#define RB_OFF HS_BYTES
#define RB_ROW 18
#define RB_BUF (32 * RB_ROW)
#define RB_NH (16 + 4 * RB_BUF)
#define XS_OFF (RB_OFF + 2 * RB_NH * 4)      // 88,192
#define SM2_BYTES (XS_OFF + 2 * 32 * 36 * 4 + 64) // 97,472 (> gemm's 81,920)

__global__ __launch_bounds__(256, 1) void fused_kernel(float* __restrict__ out) {
    extern __shared__ char smc[];
    const int bid = blockIdx.x;
    const int tid = threadIdx.x;

    // ---- pre-phase: all 148 CTAs compute M-blocks 0..47 ----
    for (int tau = bid; tau < PRE_TILES; tau += 148)
        gemm_tile(smc, tau >> 5, tau & 31);

    // ---- worker CTAs: stream remaining M-blocks 48..127 (m-major) ----
    if (bid >= 128) {
        for (int tau = PRE_TILES + (bid - 128); tau < 4096; tau += 20)
            gemm_tile(smc, tau >> 5, tau & 31);
        return;
    }

    // ---- lstm CTAs ----
    __half* hs = (__half*)smc;
    float*  rb = (float*)(smc + RB_OFF);
    float*  xs = (float*)(smc + XS_OFF);

    const int cta = bid;
    const int warp = tid >> 5, lane = tid & 31;
    const int gid = lane >> 2, tg = lane & 3;
    const int nh = warp >> 2, kh = warp & 3;

    const unsigned long long barp =
        (unsigned long long)__cvta_generic_to_global(&g_bar);
    const unsigned long long xgd0 =
        (unsigned long long)__cvta_generic_to_global(&g_xgdone[0]);

    // stage U'' fragments into registers (one-time, via hs scratch)
    unsigned aF[2][8][2][4];
    {
        __half* scr = hs;
        const __half* Ug = d_Uh + (size_t)(32 * cta) * HID;
        for (int ch = 0; ch < 2; ch++) {
            __syncthreads();
            for (int i = tid; i < 32 * 64; i += 256) {
                int row = i >> 6, seg = i & 63;
                *(float4*)(scr + row * 520 + seg * 8) =
                    *(const float4*)(Ug + row * HID + ch * 512 + seg * 8);
            }
            __syncthreads();
#pragma unroll
            for (int ks = 0; ks < 8; ks++) {
                const int kc = kh * 128 + ks * 16 + 2 * tg;
#pragma unroll
                for (int mt = 0; mt < 2; mt++) {
                    int row = mt * 16 + gid;
                    aF[ch][ks][mt][0] = *(const unsigned*)&scr[row * 520 + kc];
                    aF[ch][ks][mt][1] = *(const unsigned*)&scr[(row + 8) * 520 + kc];
                    aF[ch][ks][mt][2] = *(const unsigned*)&scr[row * 520 + kc + 8];
                    aF[ch][ks][mt][3] = *(const unsigned*)&scr[(row + 8) * 520 + kc + 8];
                }
            }
        }
        __syncthreads();
    }

    // wait until M-block 0 is complete, then prefetch xg for t=0
    if (tid == 0) {
        unsigned v;
        do {
            asm volatile("ld.acquire.gpu.global.u32 %0, [%1];"
                         : "=r"(v) : "l"(xgd0) : "memory");
        } while (v < 32u);
    }
    __syncthreads();
    {
        int row = tid >> 3, q = tid & 7;
        unsigned d = (unsigned)__cvta_generic_to_shared(xs + row * 36 + q * 4);
        CP_ASYNC_CG(d, d_xg + (size_t)row * GATES + 32 * cta + q * 4);
        CP_COMMIT();
    }

    // gate-math ownership == coalescing layout
    const int wb = 4 * warp + (lane >> 3);
    const int wu = lane & 7;
    const int wn_idx = 8 * cta + wu;
    float c_reg = 0.0f;

    float* rbd = rb + nh * RB_NH + kh * RB_BUF;
    const int nh_g = wb >> 4, bl = wb & 15;
    const float* rbg = rb + nh_g * RB_NH;

    __half* wslice = hs + warp * SLC_WARP;

    for (int t = 0; t < T_STEPS; t++) {
        const __half* hb = d_hbuf + (t & 1) * (BATCH * HID);

        // issue warp-private h slice halves (2 groups) + xg prefetch (1 group)
#pragma unroll
        for (int ch = 0; ch < 2; ch++) {
            const __half* src = hb + (size_t)(nh * 16) * HID + ch * 512 + kh * 128;
            __half* dst = wslice + ch * SLC_HALF;
#pragma unroll
            for (int it = 0; it < 8; it++) {
                int idx = lane + it * 32;
                int row = idx >> 4, seg = idx & 15;
                unsigned d = (unsigned)__cvta_generic_to_shared(
                    dst + row * SLC_ROW + seg * 8);
                CP_ASYNC_CG(d, src + (size_t)row * HID + seg * 8);
            }
            CP_COMMIT();
        }
        {
            int tn = (t + 1 < T_STEPS) ? t + 1 : T_STEPS - 1;
            int row = tid >> 3, q = tid & 7;
            unsigned d = (unsigned)__cvta_generic_to_shared(
                xs + ((t + 1) & 1) * (32 * 36) + row * 36 + q * 4);
            CP_ASYNC_CG(d, d_xg + (size_t)(tn * BATCH + row) * GATES
                            + 32 * cta + q * 4);
            CP_COMMIT();
        }

        float acc[2][2][4];
#pragma unroll
        for (int i = 0; i < 2; i++)
#pragma unroll
            for (int j = 0; j < 2; j++)
#pragma unroll
                for (int k = 0; k < 4; k++) acc[i][j][k] = 0.0f;

        auto mma_chunk = [&](int ch) {
            const __half* hc = wslice + ch * SLC_HALF;
#pragma unroll
            for (int ks = 0; ks < 8; ks++) {
                const int kcl = ks * 16 + 2 * tg;
#pragma unroll
                for (int nf = 0; nf < 2; nf++) {
                    unsigned b[2];
                    int brow = (nf * 8 + gid) * SLC_ROW;
                    b[0] = *(const unsigned*)&hc[brow + kcl];
                    b[1] = *(const unsigned*)&hc[brow + kcl + 8];
#pragma unroll
                    for (int mt = 0; mt < 2; mt++)
                        mma_f16(acc[mt][nf], aF[ch][ks][mt], b);
                }
            }
        };

        CP_WAIT(2); __syncwarp(); mma_chunk(0);
        CP_WAIT(1); __syncwarp(); mma_chunk(1);

        // single-phase reduce
#pragma unroll
        for (int mt = 0; mt < 2; mt++)
#pragma unroll
            for (int nf = 0; nf < 2; nf++) {
                int row = mt * 16 + gid;
                int col = nf * 8 + 2 * tg;
                rbd[row * RB_ROW + col]           = acc[mt][nf][0];
                rbd[row * RB_ROW + col + 1]       = acc[mt][nf][1];
                rbd[(row + 8) * RB_ROW + col]     = acc[mt][nf][2];
                rbd[(row + 8) * RB_ROW + col + 1] = acc[mt][nf][3];
            }
        __syncthreads();   // S_reduce

        // gate math — owner (wb, wu) stores directly
        float hval, c_save;
        {
            const float* xgr = xs + (t & 1) * (32 * 36) + wb * 36;
            float v[4];
#pragma unroll
            for (int gate = 0; gate < 4; gate++) {
                int r = gate * 8 + wu;
                float s = xgr[r];
#pragma unroll
                for (int p = 0; p < 4; p++)
                    s += rbg[p * RB_BUF + r * RB_ROW + bl];
                v[gate] = s;
            }
            float it = sigm_f(v[0]);
            float ft = sigm_f(v[1]);
            float ch = tanh_f(v[2]);
            float ot = sigm_f(v[3]);
            c_reg = ft * c_reg + it * ch;
            c_save = c_reg;
            hval = ot * tanh_f(c_reg);
        }

        if (t + 1 < T_STEPS)
            d_hbuf[((t + 1) & 1) * (BATCH * HID) + wb * HID + wn_idx]
                = __float2half_rn(hval);

        __syncthreads();   // S_prerelease: order h stores before release
        if (tid == 0)
            asm volatile("red.release.gpu.global.add.u32 [%0], %1;"
                         :: "l"(barp), "r"(1u) : "memory");

        // out stores overlap the barrier spin
        out[(size_t)t * (BATCH * HID) + wb * HID + wn_idx] = hval;
        if (t == T_STEPS - 1) {
            out[16777216 + wb * HID + wn_idx] = hval;           // h_n
            out[16777216 + 32768 + wb * HID + wn_idx] = c_save; // c_n
        }

        if (tid == 0) {
            // step barrier
            const unsigned target = 128u * (unsigned)(t + 1);
            unsigned v;
            do {
                asm volatile("ld.acquire.gpu.global.u32 %0, [%1];"
                             : "=r"(v) : "l"(barp) : "memory");
            } while (v < target);
            // xg readiness for the prefetch issued at the top of step t+1
            int tpre = (t + 2 < T_STEPS) ? t + 2 : T_STEPS - 1;
            unsigned long long cp = xgd0 + (unsigned long long)((tpre >> 2) * 32) * 4;
            do {
                asm volatile("ld.acquire.gpu.global.u32 %0, [%1];"
                             : "=r"(v) : "l"(cp) : "memory");
            } while (v < 32u);
        }
        __syncthreads();   // S_spin
    }
}

// ---------------------------------------------------------------------------
extern "C" void kernel_launch(void* const* d_in, const int* in_sizes, int n_in,
                              void* d_out, int out_size) {
    (void)in_sizes; (void)n_in; (void)out_size;
    const float* x   = (const float*)d_in[0];
    const float* W   = (const float*)d_in[1];
    const float* U   = (const float*)d_in[2];
    const float* bih = (const float*)d_in[3];
    const float* bhh = (const float*)d_in[4];
    float* out = (float*)d_out;

    static int inited = 0;
    const int smem2 = SM2_BYTES;                  // 97,472
    if (!inited) {
        cudaFuncSetAttribute(fused_kernel, cudaFuncAttributeMaxDynamicSharedMemorySize, smem2);
        inited = 1;
    }

    prep_kernel<<<4096, 256>>>(x, W, U, bih, bhh);
    fused_kernel<<<148, 256, smem2>>>(out);
}

// round 16
// speedup vs baseline: 1.3952x; 1.3952x over previous
#include <cuda_runtime.h>
#include <cuda_fp16.h>

// ---------------------------------------------------------------------------
// LSTM_6786048328562 : T=512, B=32, I=H=1024  (fp32 in/out, fp16 tensor math
//   with fp32 accumulate)
//   out = [ output(512*32*1024) | h_n(32*1024) | c_n(32*1024) ]
//
// Row reorder:  j'' = 32*blk + gate*8 + u   (hidden n = 8*blk + u, blk=0..127)
//
// prep    : reorder+fp16-round W,U; fp16 x; bias; zero h; group counters = 0
// gemm_xg : xg = xh @ Wh''^T + bias (m16n8k16 f16 mma, 128x128x32, 4-stage)
// lstm    : persistent 128 CTAs. Warp (nh,kh) owns a disjoint h slice
//           (16 b x 256 k). DEPENDENCY-EXACT SYNC: warp kh's slice is
//           produced by the 32 CTAs with (cta>>4)&3 == kh, so each CTA
//           releases ONE group counter and each warp acquire-polls only its
//           producer group — no chip-wide barrier, spread absorbed per-group,
//           max skew 1 step (bounded by the CTA-wide reduce sync).
// ---------------------------------------------------------------------------

#define T_STEPS 512
#define BATCH   32
#define HID     1024
#define GATES   4096

__device__ float  d_xg[67108864];            // [16384][4096] fp32
__device__ __half d_xh[16777216];            // fp16 x
__device__ __half d_Wh[GATES * HID];
__device__ __half d_Uh[GATES * HID];
__device__ float  d_biasp[GATES];
__device__ __half d_hbuf[2 * BATCH * HID];   // double-buffered h (fp16)
__device__ unsigned g_grp[4 * 32];           // 4 group counters, 128B stride

__device__ __forceinline__ void mma_f16(float* c, const unsigned* a, const unsigned* b) {
    asm volatile(
        "mma.sync.aligned.m16n8k16.row.col.f32.f16.f16.f32 "
        "{%0,%1,%2,%3}, {%4,%5,%6,%7}, {%8,%9}, {%0,%1,%2,%3};\n"
        : "+f"(c[0]), "+f"(c[1]), "+f"(c[2]), "+f"(c[3])
        : "r"(a[0]), "r"(a[1]), "r"(a[2]), "r"(a[3]), "r"(b[0]), "r"(b[1]));
}

__device__ __forceinline__ float sigm_f(float x) {
    float e = __expf(-x);
    return __fdividef(1.0f, 1.0f + e);
}
__device__ __forceinline__ float tanh_f(float x) {
    float xc = fminf(fmaxf(x, -10.0f), 10.0f);
    float e = __expf(2.0f * xc);
    return __fdividef(e - 1.0f, e + 1.0f);
}

#define CP_ASYNC_CG(dst, src) \
    asm volatile("cp.async.cg.shared.global [%0], [%1], 16;\n" :: "r"(dst), "l"(src))
#define CP_COMMIT() asm volatile("cp.async.commit_group;\n")
#define CP_WAIT(n)  asm volatile("cp.async.wait_group %0;\n" :: "n"(n))

// ---------------------------------------------------------------------------
__global__ void prep_kernel(const float* __restrict__ x,
                            const float* __restrict__ W, const float* __restrict__ U,
                            const float* __restrict__ bih, const float* __restrict__ bhh) {
    int tid = blockIdx.x * blockDim.x + threadIdx.x;
    int stride = gridDim.x * blockDim.x;
    if (tid < 4 * 32) g_grp[tid] = 0u;

    for (int idx = tid; idx < GATES * HID; idx += stride) {
        int jp = idx >> 10, k = idx & 1023;
        int blk = jp >> 5, r = jp & 31;
        int gate = r >> 3, u = r & 7;
        int j = gate * HID + (blk * 8 + u);
        d_Wh[idx] = __float2half_rn(W[j * HID + k]);
        d_Uh[idx] = __float2half_rn(U[j * HID + k]);
    }
    for (int idx = tid; idx < 16777216; idx += stride)
        d_xh[idx] = __float2half_rn(x[idx]);
    for (int idx = tid; idx < GATES; idx += stride) {
        int blk = idx >> 5, r = idx & 31;
        int gate = r >> 3, u = r & 7;
        int j = gate * HID + (blk * 8 + u);
        d_biasp[idx] = bih[j] + bhh[j];
    }
    for (int idx = tid; idx < 2 * BATCH * HID; idx += stride)
        d_hbuf[idx] = __float2half_rn(0.0f);
}

// ---------------------------------------------------------------------------
// Phase 1: xg = xh @ Wh^T + bias   (M=16384, N=4096, K=1024), fp16 mma.
// 128x128 CTA tile, BK=32, 8 warps (2m x 4n), 4-stage cp.async pipeline.
// ---------------------------------------------------------------------------
#define P1H 40
#define P1_STAGE (128 * P1H)

__global__ __launch_bounds__(256, 2) void gemm_xg() {
    extern __shared__ __half sm1[];
    __half* As = sm1;
    __half* Bs = sm1 + 4 * P1_STAGE;

    const int n0 = blockIdx.x * 128;
    const int m0 = blockIdx.y * 128;
    const int tid = threadIdx.x;
    const int warp = tid >> 5, lane = tid & 31;
    const int wm = warp >> 2, wn = warp & 3;
    const int gid = lane >> 2, tg = lane & 3;

    float acc[4][4][4];
#pragma unroll
    for (int i = 0; i < 4; i++)
#pragma unroll
        for (int j = 0; j < 4; j++)
#pragma unroll
            for (int k = 0; k < 4; k++) acc[i][j][k] = 0.0f;

    const __half* Ag = d_xh + (size_t)m0 * HID;
    const __half* Bg = d_Wh + (size_t)n0 * HID;

    auto load_stage = [&](int kt, int st) {
        __half* Ad = As + st * P1_STAGE;
        __half* Bd = Bs + st * P1_STAGE;
        const int k0 = kt * 32;
#pragma unroll
        for (int l = 0; l < 2; l++) {
            int i = tid + l * 256;
            int row = i >> 2, seg = i & 3;
            unsigned da = (unsigned)__cvta_generic_to_shared(Ad + row * P1H + seg * 8);
            CP_ASYNC_CG(da, Ag + (size_t)row * HID + k0 + seg * 8);
            unsigned db = (unsigned)__cvta_generic_to_shared(Bd + row * P1H + seg * 8);
            CP_ASYNC_CG(db, Bg + (size_t)row * HID + k0 + seg * 8);
        }
        CP_COMMIT();
    };

    load_stage(0, 0);
    load_stage(1, 1);
    load_stage(2, 2);
    for (int kt = 0; kt < 32; kt++) {
        if (kt < 30)       { CP_WAIT(2); }
        else if (kt == 30) { CP_WAIT(1); }
        else               { CP_WAIT(0); }
        __syncthreads();
        if (kt + 3 < 32) load_stage(kt + 3, (kt + 3) & 3);

        const __half* Ac = As + (kt & 3) * P1_STAGE;
        const __half* Bc = Bs + (kt & 3) * P1_STAGE;
#pragma unroll
        for (int ks = 0; ks < 2; ks++) {
            const int kb = ks * 16;
            unsigned a[4][4], b[4][2];
#pragma unroll
            for (int mf = 0; mf < 4; mf++) {
                int row = wm * 64 + mf * 16 + gid;
                a[mf][0] = *(const unsigned*)&Ac[row * P1H + kb + 2 * tg];
                a[mf][1] = *(const unsigned*)&Ac[(row + 8) * P1H + kb + 2 * tg];
                a[mf][2] = *(const unsigned*)&Ac[row * P1H + kb + 8 + 2 * tg];
                a[mf][3] = *(const unsigned*)&Ac[(row + 8) * P1H + kb + 8 + 2 * tg];
            }
#pragma unroll
            for (int nf = 0; nf < 4; nf++) {
                int col = wn * 32 + nf * 8 + gid;
                b[nf][0] = *(const unsigned*)&Bc[col * P1H + kb + 2 * tg];
                b[nf][1] = *(const unsigned*)&Bc[col * P1H + kb + 8 + 2 * tg];
            }
#pragma unroll
            for (int mf = 0; mf < 4; mf++)
#pragma unroll
                for (int nf = 0; nf < 4; nf++) mma_f16(acc[mf][nf], a[mf], b[nf]);
        }
    }
    __syncthreads();

#pragma unroll
    for (int mf = 0; mf < 4; mf++)
#pragma unroll
        for (int nf = 0; nf < 4; nf++) {
            int row = m0 + wm * 64 + mf * 16 + gid;
            int col = n0 + wn * 32 + nf * 8 + 2 * tg;
            float b0 = d_biasp[col], b1 = d_biasp[col + 1];
            d_xg[(size_t)row * GATES + col]           = acc[mf][nf][0] + b0;
            d_xg[(size_t)row * GATES + col + 1]       = acc[mf][nf][1] + b1;
            d_xg[(size_t)(row + 8) * GATES + col]     = acc[mf][nf][2] + b0;
            d_xg[(size_t)(row + 8) * GATES + col + 1] = acc[mf][nf][3] + b1;
        }
}

// ---------------------------------------------------------------------------
// Phase 2: persistent recurrence, fp16 MMA. 128 CTAs, 32 gate-rows, full K.
// Warp w: nh = w>>2 (batch half), kh = w&3 (K quarter). Warp-private h slice.
// Sync: group counter per K-quarter producer set ((cta>>4)&3).
// ---------------------------------------------------------------------------
#define SLC_ROW 136
#define SLC_HALF (16 * SLC_ROW)
#define SLC_WARP (2 * SLC_HALF)
#define HS_BYTES (8 * SLC_WARP * 2)          // 69,632
#define RB_OFF HS_BYTES
#define RB_ROW 18
#define RB_BUF (32 * RB_ROW)
#define RB_NH (16 + 4 * RB_BUF)
#define XS_OFF (RB_OFF + 2 * RB_NH * 4)      // 88,192
#define SM2_BYTES (XS_OFF + 2 * 32 * 36 * 4 + 64) // 97,472

__global__ __launch_bounds__(256, 1) void lstm_kernel(float* __restrict__ out) {
    extern __shared__ char smc[];
    __half* hs = (__half*)smc;
    float*  rb = (float*)(smc + RB_OFF);
    float*  xs = (float*)(smc + XS_OFF);

    const int cta = blockIdx.x;
    const int tid = threadIdx.x;
    const int warp = tid >> 5, lane = tid & 31;
    const int gid = lane >> 2, tg = lane & 3;
    const int nh = warp >> 2, kh = warp & 3;

    // my producer group: this CTA's hidden units feed K-quarter (cta>>4)&3
    const int mygrp = (cta >> 4) & 3;
    const unsigned long long myrel = (unsigned long long)
        __cvta_generic_to_global(&g_grp[mygrp * 32]);
    const unsigned long long pollp = (unsigned long long)
        __cvta_generic_to_global(&g_grp[kh * 32]);

    // ---- stage U'' fragments into registers (one-time, via hs scratch) ----
    unsigned aF[2][8][2][4];
    {
        __half* scr = hs;
        const __half* Ug = d_Uh + (size_t)(32 * cta) * HID;
        for (int ch = 0; ch < 2; ch++) {
            for (int i = tid; i < 32 * 64; i += 256) {
                int row = i >> 6, seg = i & 63;
                *(float4*)(scr + row * 520 + seg * 8) =
                    *(const float4*)(Ug + row * HID + ch * 512 + seg * 8);
            }
            __syncthreads();
#pragma unroll
            for (int ks = 0; ks < 8; ks++) {
                const int kc = kh * 128 + ks * 16 + 2 * tg;
#pragma unroll
                for (int mt = 0; mt < 2; mt++) {
                    int row = mt * 16 + gid;
                    aF[ch][ks][mt][0] = *(const unsigned*)&scr[row * 520 + kc];
                    aF[ch][ks][mt][1] = *(const unsigned*)&scr[(row + 8) * 520 + kc];
                    aF[ch][ks][mt][2] = *(const unsigned*)&scr[row * 520 + kc + 8];
                    aF[ch][ks][mt][3] = *(const unsigned*)&scr[(row + 8) * 520 + kc + 8];
                }
            }
            __syncthreads();
        }
    }

    // prefetch xg for t=0 into xs[0]
    {
        int row = tid >> 3, q = tid & 7;
        unsigned d = (unsigned)__cvta_generic_to_shared(xs + row * 36 + q * 4);
        CP_ASYNC_CG(d, d_xg + (size_t)row * GATES + 32 * cta + q * 4);
        CP_COMMIT();
    }

    // gate-math ownership == coalescing layout
    const int wb = 4 * warp + (lane >> 3);
    const int wu = lane & 7;
    const int wn_idx = 8 * cta + wu;
    float c_reg = 0.0f;

    float* rbd = rb + nh * RB_NH + kh * RB_BUF;
    const int nh_g = wb >> 4, bl = wb & 15;
    const float* rbg = rb + nh_g * RB_NH;

    __half* wslice = hs + warp * SLC_WARP;

    for (int t = 0; t < T_STEPS; t++) {
        const __half* hb = d_hbuf + (t & 1) * (BATCH * HID);

        // wait for THIS warp's producer group (32 CTAs) to finish step t-1.
        // All lanes acquire-load the same counter (1 coalesced request).
        if (t) {
            const unsigned target = 32u * (unsigned)t;
            unsigned v;
            do {
                asm volatile("ld.acquire.gpu.global.u32 %0, [%1];"
                             : "=r"(v) : "l"(pollp) : "memory");
            } while (v < target);
        }

        // issue warp-private h slice halves (2 groups) + xg prefetch (1 group)
#pragma unroll
        for (int ch = 0; ch < 2; ch++) {
            const __half* src = hb + (size_t)(nh * 16) * HID + ch * 512 + kh * 128;
            __half* dst = wslice + ch * SLC_HALF;
#pragma unroll
            for (int it = 0; it < 8; it++) {
                int idx = lane + it * 32;
                int row = idx >> 4, seg = idx & 15;
                unsigned d = (unsigned)__cvta_generic_to_shared(
                    dst + row * SLC_ROW + seg * 8);
                CP_ASYNC_CG(d, src + (size_t)row * HID + seg * 8);
            }
            CP_COMMIT();
        }
        {
            int tn = (t + 1 < T_STEPS) ? t + 1 : T_STEPS - 1;
            int row = tid >> 3, q = tid & 7;
            unsigned d = (unsigned)__cvta_generic_to_shared(
                xs + ((t + 1) & 1) * (32 * 36) + row * 36 + q * 4);
            CP_ASYNC_CG(d, d_xg + (size_t)(tn * BATCH + row) * GATES
                            + 32 * cta + q * 4);
            CP_COMMIT();
        }

        float acc[2][2][4];
#pragma unroll
        for (int i = 0; i < 2; i++)
#pragma unroll
            for (int j = 0; j < 2; j++)
#pragma unroll
                for (int k = 0; k < 4; k++) acc[i][j][k] = 0.0f;

        auto mma_chunk = [&](int ch) {
            const __half* hc = wslice + ch * SLC_HALF;
#pragma unroll
            for (int ks = 0; ks < 8; ks++) {
                const int kcl = ks * 16 + 2 * tg;
#pragma unroll
                for (int nf = 0; nf < 2; nf++) {
                    unsigned b[2];
                    int brow = (nf * 8 + gid) * SLC_ROW;
                    b[0] = *(const unsigned*)&hc[brow + kcl];
                    b[1] = *(const unsigned*)&hc[brow + kcl + 8];
#pragma unroll
                    for (int mt = 0; mt < 2; mt++)
                        mma_f16(acc[mt][nf], aF[ch][ks][mt], b);
                }
            }
        };

        CP_WAIT(2); __syncwarp(); mma_chunk(0);
        CP_WAIT(1); __syncwarp(); mma_chunk(1);

        // single-phase reduce
#pragma unroll
        for (int mt = 0; mt < 2; mt++)
#pragma unroll
            for (int nf = 0; nf < 2; nf++) {
                int row = mt * 16 + gid;
                int col = nf * 8 + 2 * tg;
                rbd[row * RB_ROW + col]           = acc[mt][nf][0];
                rbd[row * RB_ROW + col + 1]       = acc[mt][nf][1];
                rbd[(row + 8) * RB_ROW + col]     = acc[mt][nf][2];
                rbd[(row + 8) * RB_ROW + col + 1] = acc[mt][nf][3];
            }
        __syncthreads();   // S_reduce

        // gate math — owner (wb, wu) stores directly
        float hval, c_save;
        {
            const float* xgr = xs + (t & 1) * (32 * 36) + wb * 36;
            float v[4];
#pragma unroll
            for (int gate = 0; gate < 4; gate++) {
                int r = gate * 8 + wu;
                float s = xgr[r];
#pragma unroll
                for (int p = 0; p < 4; p++)
                    s += rbg[p * RB_BUF + r * RB_ROW + bl];
                v[gate] = s;
            }
            float it = sigm_f(v[0]);
            float ft = sigm_f(v[1]);
            float ch = tanh_f(v[2]);
            float ot = sigm_f(v[3]);
            c_reg = ft * c_reg + it * ch;
            c_save = c_reg;
            hval = ot * tanh_f(c_reg);
        }

        if (t + 1 < T_STEPS)
            d_hbuf[((t + 1) & 1) * (BATCH * HID) + wb * HID + wn_idx]
                = __float2half_rn(hval);

        __syncthreads();   // S_prerelease: order all warps' h stores
        if (tid == 0)
            asm volatile("red.release.gpu.global.add.u32 [%0], %1;"
                         :: "l"(myrel), "r"(1u) : "memory");

        // out stores overlap the next step's group poll
        out[(size_t)t * (BATCH * HID) + wb * HID + wn_idx] = hval;
        if (t == T_STEPS - 1) {
            out[16777216 + wb * HID + wn_idx] = hval;           // h_n
            out[16777216 + 32768 + wb * HID + wn_idx] = c_save; // c_n
        }
        // no chip-wide barrier: each warp's poll at the next loop top gates it
    }
}

// ---------------------------------------------------------------------------
extern "C" void kernel_launch(void* const* d_in, const int* in_sizes, int n_in,
                              void* d_out, int out_size) {
    (void)in_sizes; (void)n_in; (void)out_size;
    const float* x   = (const float*)d_in[0];
    const float* W   = (const float*)d_in[1];
    const float* U   = (const float*)d_in[2];
    const float* bih = (const float*)d_in[3];
    const float* bhh = (const float*)d_in[4];
    float* out = (float*)d_out;

    static int inited = 0;
    const int smem1 = 4 * 2 * P1_STAGE * 2;       // 81,920
    const int smem2 = SM2_BYTES;                  // 97,472
    if (!inited) {
        cudaFuncSetAttribute(gemm_xg, cudaFuncAttributeMaxDynamicSharedMemorySize, smem1);
        cudaFuncSetAttribute(lstm_kernel, cudaFuncAttributeMaxDynamicSharedMemorySize, smem2);
        inited = 1;
    }

    prep_kernel<<<4096, 256>>>(x, W, U, bih, bhh);
    dim3 g1(32, 128);
    gemm_xg<<<g1, 256, smem1>>>();
    lstm_kernel<<<128, 256, smem2>>>(out);
}